// round 11
// baseline (speedup 1.0000x reference)
#include <cuda_runtime.h>
#include <cuda_bf16.h>
#include <cstdint>
#include <math.h>

// Problem constants
#define NB   2048
#define NM   64
#define NHID 1024
#define NH   8
#define ND   128

// ---------------------------------------------------------------------------
// Device scratch (allocation-free rule): bf16 hi/lo planes
// ---------------------------------------------------------------------------
__device__ __align__(256) __nv_bfloat16 g_qs_hi [NB * NHID];
__device__ __align__(256) __nv_bfloat16 g_qs_lo [NB * NHID];
__device__ __align__(256) __nv_bfloat16 g_Wq_hi [NHID * NHID];
__device__ __align__(256) __nv_bfloat16 g_Wq_lo [NHID * NHID];
__device__ __align__(256) __nv_bfloat16 g_Wb_hi [ND * ND];
__device__ __align__(256) __nv_bfloat16 g_Wb_lo [ND * ND];
__device__ __align__(256) __nv_bfloat16 g_Wkt_hi[NH * NHID * ND];  // [h][j][d]
__device__ __align__(256) __nv_bfloat16 g_Wkt_lo[NH * NHID * ND];
__device__ __align__(256) __nv_bfloat16 g_Wv_hi [NHID * NHID];
__device__ __align__(256) __nv_bfloat16 g_Wv_lo [NHID * NHID];
__device__ __align__(256) __nv_bfloat16 g_Wo_hi [NHID * NHID];
__device__ __align__(256) __nv_bfloat16 g_Wo_lo [NHID * NHID];
__device__ __align__(256) __nv_bfloat16 g_qp_hi [NB * NHID];
__device__ __align__(256) __nv_bfloat16 g_qp_lo [NB * NHID];
__device__ __align__(256) __nv_bfloat16 g_qb_hi [NB * NHID];
__device__ __align__(256) __nv_bfloat16 g_qb_lo [NB * NHID];
__device__ __align__(256) __nv_bfloat16 g_qt_hi [NB * NH * NHID];
__device__ __align__(256) __nv_bfloat16 g_qt_lo [NB * NH * NHID];
__device__ __align__(256) __nv_bfloat16 g_y_hi  [NB * NH * NHID];
__device__ __align__(256) __nv_bfloat16 g_y_lo  [NB * NH * NHID];
__device__ __align__(256) __nv_bfloat16 g_x_hi  [NB * NHID];
__device__ __align__(256) __nv_bfloat16 g_x_lo  [NB * NHID];

// ---------------------------------------------------------------------------
// Helpers
// ---------------------------------------------------------------------------
__device__ __forceinline__ uint32_t pack2(__nv_bfloat16 a, __nv_bfloat16 b) {
    uint16_t ua = *reinterpret_cast<uint16_t*>(&a);
    uint16_t ub = *reinterpret_cast<uint16_t*>(&b);
    return (uint32_t)ua | ((uint32_t)ub << 16);
}

__device__ __forceinline__ void split1(float v, __nv_bfloat16& h, __nv_bfloat16& l) {
    h = __float2bfloat16(v);
    l = __float2bfloat16(v - __bfloat162float(h));
}

__device__ __forceinline__ void cpa16s(uint32_t s, const void* g) {
    asm volatile("cp.async.cg.shared.global [%0], [%1], 16;\n" :: "r"(s), "l"(g));
}
__device__ __forceinline__ void cpa_commit() {
    asm volatile("cp.async.commit_group;\n");
}
template <int N>
__device__ __forceinline__ void cpa_wait() {
    asm volatile("cp.async.wait_group %0;\n" :: "n"(N));
}

__device__ __forceinline__ void mma_bf16(float* c, const uint32_t* a,
                                         uint32_t b0, uint32_t b1) {
    asm volatile(
        "mma.sync.aligned.m16n8k16.row.col.f32.bf16.bf16.f32 "
        "{%0,%1,%2,%3}, {%4,%5,%6,%7}, {%8,%9}, {%0,%1,%2,%3};\n"
        : "+f"(c[0]), "+f"(c[1]), "+f"(c[2]), "+f"(c[3])
        : "r"(a[0]), "r"(a[1]), "r"(a[2]), "r"(a[3]),
          "r"(b0), "r"(b1));
}

__device__ __forceinline__ void ldsm4(uint32_t* r, uint32_t addr) {
    asm volatile(
        "ldmatrix.sync.aligned.m8n8.x4.shared.b16 {%0,%1,%2,%3}, [%4];\n"
        : "=r"(r[0]), "=r"(r[1]), "=r"(r[2]), "=r"(r[3])
        : "r"(addr));
}

// ---- packed f32x2 (sm_100+ family feature; FFMA2 in SASS) ----
__device__ __forceinline__ uint64_t f2u(float a, float b) {
    uint64_t r;
    asm("mov.b64 %0, {%1, %2};" : "=l"(r) : "f"(a), "f"(b));
    return r;
}
__device__ __forceinline__ float2 u2f(uint64_t v) {
    float2 f;
    asm("mov.b64 {%0, %1}, %2;" : "=f"(f.x), "=f"(f.y) : "l"(v));
    return f;
}
__device__ __forceinline__ void ffma2(uint64_t& d, uint64_t a, uint64_t b) {
    asm("fma.rn.f32x2 %0, %1, %2, %0;" : "+l"(d) : "l"(a), "l"(b));
}

// ---------------------------------------------------------------------------
// Conversion kernels (R4-exact)
// ---------------------------------------------------------------------------
__global__ void __launch_bounds__(256) split_f32(
    const float* __restrict__ src, __nv_bfloat16* __restrict__ hi,
    __nv_bfloat16* __restrict__ lo, int n4)
{
    int i = blockIdx.x * 256 + threadIdx.x;
    if (i >= n4) return;
    float4 f = ((const float4*)src)[i];
    float vv[4] = {f.x, f.y, f.z, f.w};
    __nv_bfloat16 h[4], l[4];
    #pragma unroll
    for (int j = 0; j < 4; j++) split1(vv[j], h[j], l[j]);
    uint2 uh, ul;
    uh.x = pack2(h[0], h[1]); uh.y = pack2(h[2], h[3]);
    ul.x = pack2(l[0], l[1]); ul.y = pack2(l[2], l[3]);
    ((uint2*)hi)[i] = uh;
    ((uint2*)lo)[i] = ul;
}

// Transpose + split Wk: out[h][j][d] = Wk[h*ND + d][j]
__global__ void __launch_bounds__(256) tsplit_wk(
    const float* __restrict__ Wk, __nv_bfloat16* __restrict__ hi,
    __nv_bfloat16* __restrict__ lo)
{
    __shared__ float t[32][33];
    const int h  = blockIdx.z;
    const int d0 = blockIdx.y * 32;
    const int j0 = blockIdx.x * 32;
    const int tx = threadIdx.x & 31;
    const int ty = threadIdx.x >> 5;
    #pragma unroll
    for (int r = ty; r < 32; r += 8)
        t[r][tx] = Wk[(long)(h * ND + d0 + r) * NHID + j0 + tx];
    __syncthreads();
    #pragma unroll
    for (int r = ty; r < 32; r += 8) {
        float v = t[tx][r];
        __nv_bfloat16 hb, lb;
        split1(v, hb, lb);
        long o = (long)h * NHID * ND + (long)(j0 + r) * ND + d0 + tx;
        hi[o] = hb;
        lo[o] = lb;
    }
}

// ---------------------------------------------------------------------------
// GEMM v3 (R4-exact): C[M,N] = A[M,K] @ B[N,K]^T, split-bf16 x3, ldmatrix.
// Tiles BM=128, BN=128, BK=32. 256 threads = 8 warps (2 M x 4 N), warp 64x32.
// ---------------------------------------------------------------------------
#define SK 40
#define PLANE_B (128 * SK * 2)        // 10240 bytes per plane
#define STAGE_B (4 * PLANE_B)         // 40960 bytes per stage
#define GEMM_SMEM (2 * STAGE_B)       // 81920 bytes

__device__ __forceinline__ void gemm_issue(
    uint32_t sb,
    const __nv_bfloat16* __restrict__ Ah, const __nv_bfloat16* __restrict__ Al, int lda,
    const __nv_bfloat16* __restrict__ Bh, const __nv_bfloat16* __restrict__ Bl, int ldb,
    int m0, int n0, int kk, int tid)
{
    #pragma unroll
    for (int i = 0; i < 2; i++) {
        const int c   = tid + i * 256;        // 0..511
        const int row = c >> 2;
        const int col = c & 3;                // 16B chunk within 64B row
        const uint32_t so = row * 80 + col * 16;
        const long ga = (long)(m0 + row) * lda + kk + col * 8;
        cpa16s(sb + so,               Ah + ga);
        cpa16s(sb + PLANE_B + so,     Al + ga);
        const long gb = (long)(n0 + row) * ldb + kk + col * 8;
        cpa16s(sb + 2 * PLANE_B + so, Bh + gb);
        cpa16s(sb + 3 * PLANE_B + so, Bl + gb);
    }
    cpa_commit();
}

__global__ void __launch_bounds__(256) gemm_ldsm(
    const __nv_bfloat16* __restrict__ Ah, const __nv_bfloat16* __restrict__ Al,
    int lda, long strideAh,
    const __nv_bfloat16* __restrict__ Bh, const __nv_bfloat16* __restrict__ Bl,
    int ldb, long strideBh,
    float* __restrict__ Cf, __nv_bfloat16* __restrict__ Chi, __nv_bfloat16* __restrict__ Clo,
    int ldc, long strideCh,
    int K, const float* __restrict__ bias)
{
    extern __shared__ __align__(16) char dsm[];

    const int h = blockIdx.z;
    Ah += (long)h * strideAh;  Al += (long)h * strideAh;
    Bh += (long)h * strideBh;  Bl += (long)h * strideBh;
    if (Cf)  Cf  += (long)h * strideCh;
    if (Chi) { Chi += (long)h * strideCh; Clo += (long)h * strideCh; }

    const int m0 = blockIdx.x * 128;
    const int n0 = blockIdx.y * 128;
    const int tid  = threadIdx.x;
    const int lane = tid & 31;
    const int warp = tid >> 5;
    const int wm = warp & 1;    // 2 warps along M (64 rows each)
    const int wn = warp >> 1;   // 4 warps along N (32 cols each)

    const uint32_t sbase = (uint32_t)__cvta_generic_to_shared(dsm);

    float acc[4][4][4];
    #pragma unroll
    for (int i = 0; i < 4; i++)
        #pragma unroll
        for (int j = 0; j < 4; j++)
            #pragma unroll
            for (int l = 0; l < 4; l++) acc[i][j][l] = 0.f;

    const int nk = K >> 5;

    gemm_issue(sbase, Ah, Al, lda, Bh, Bl, ldb, m0, n0, 0, tid);

    const int lg = lane >> 3;
    const int lr = lane & 7;
    const uint32_t a_row_off = ((lg & 1) * 8 + lr) * 80 + (lg >> 1) * 16;

    for (int ks = 0; ks < nk; ks++) {
        if (ks + 1 < nk) {
            gemm_issue(sbase + ((ks + 1) & 1) * STAGE_B, Ah, Al, lda, Bh, Bl, ldb,
                       m0, n0, (ks + 1) << 5, tid);
            cpa_wait<1>();
        } else {
            cpa_wait<0>();
        }
        __syncthreads();

        const uint32_t st = sbase + (ks & 1) * STAGE_B;
        const uint32_t sAhi = st;
        const uint32_t sAlo = st + PLANE_B;
        const uint32_t sBhi = st + 2 * PLANE_B;
        const uint32_t sBlo = st + 3 * PLANE_B;

        #pragma unroll
        for (int kf = 0; kf < 2; kf++) {
            const uint32_t kb2 = kf * 32;   // byte offset of k16 slice
            uint32_t ahi[4][4], alo[4][4];
            uint32_t bhi[4][2], blo[4][2];

            #pragma unroll
            for (int mt = 0; mt < 4; mt++) {
                const uint32_t ro = (wm * 64 + mt * 16) * 80 + a_row_off + kb2;
                ldsm4(ahi[mt], sAhi + ro);
                ldsm4(alo[mt], sAlo + ro);
            }
            #pragma unroll
            for (int pt = 0; pt < 2; pt++) {
                const uint32_t ro = (wn * 32 + pt * 16) * 80 + a_row_off + kb2;
                uint32_t rh[4], rl[4];
                ldsm4(rh, sBhi + ro);
                ldsm4(rl, sBlo + ro);
                bhi[pt * 2][0]     = rh[0]; bhi[pt * 2][1]     = rh[2];
                bhi[pt * 2 + 1][0] = rh[1]; bhi[pt * 2 + 1][1] = rh[3];
                blo[pt * 2][0]     = rl[0]; blo[pt * 2][1]     = rl[2];
                blo[pt * 2 + 1][0] = rl[1]; blo[pt * 2 + 1][1] = rl[3];
            }

            #pragma unroll
            for (int mt = 0; mt < 4; mt++)
                #pragma unroll
                for (int nt = 0; nt < 4; nt++) {
                    mma_bf16(acc[mt][nt], ahi[mt], bhi[nt][0], bhi[nt][1]);  // hi*hi
                    mma_bf16(acc[mt][nt], ahi[mt], blo[nt][0], blo[nt][1]);  // hi*lo
                    mma_bf16(acc[mt][nt], alo[mt], bhi[nt][0], bhi[nt][1]);  // lo*hi
                }
        }
        __syncthreads();
    }

    // ---- epilogue ----
    const int g  = lane >> 2;
    const int tc = (lane & 3) * 2;
    #pragma unroll
    for (int mt = 0; mt < 4; mt++)
        #pragma unroll
        for (int nt = 0; nt < 4; nt++) {
            const int r = m0 + wm * 64 + mt * 16 + g;
            const int c = n0 + wn * 32 + nt * 8 + tc;
            float b0 = 0.f, b1 = 0.f;
            if (bias) { b0 = bias[c]; b1 = bias[c + 1]; }
            float v00 = acc[mt][nt][0] + b0, v01 = acc[mt][nt][1] + b1;
            float v10 = acc[mt][nt][2] + b0, v11 = acc[mt][nt][3] + b1;
            if (Cf) {
                *(float2*)(Cf + (long)r * ldc + c)       = make_float2(v00, v01);
                *(float2*)(Cf + (long)(r + 8) * ldc + c) = make_float2(v10, v11);
            } else {
                __nv_bfloat16 h0, l0, h1, l1;
                split1(v00, h0, l0); split1(v01, h1, l1);
                *(uint32_t*)(Chi + (long)r * ldc + c) = pack2(h0, h1);
                *(uint32_t*)(Clo + (long)r * ldc + c) = pack2(l0, l1);
                split1(v10, h0, l0); split1(v11, h1, l1);
                *(uint32_t*)(Chi + (long)(r + 8) * ldc + c) = pack2(h0, h1);
                *(uint32_t*)(Clo + (long)(r + 8) * ldc + c) = pack2(l0, l1);
            }
        }
}

// ---------------------------------------------------------------------------
// Streaming attention (R4 structure/occ=2; inner loops on packed f32x2 FFMA2)
// ---------------------------------------------------------------------------
__global__ void __launch_bounds__(256, 2) attn_stream(
    const __nv_bfloat16* __restrict__ qthi, const __nv_bfloat16* __restrict__ qtlo,
    const float* __restrict__ k, const float* __restrict__ v,
    __nv_bfloat16* __restrict__ yhi, __nv_bfloat16* __restrict__ ylo)
{
    __shared__ __align__(16) float s_qt[NH * NHID];
    __shared__ __align__(16) float s_p[NH][NM];

    const int b    = blockIdx.x;
    const int tid  = threadIdx.x;
    const int lane = tid & 31;
    const int w    = tid >> 5;

    {
        const __nv_bfloat16* qh = qthi + (long)b * (NH * NHID);
        const __nv_bfloat16* ql = qtlo + (long)b * (NH * NHID);
        #pragma unroll
        for (int i = 0; i < 4; i++) {
            const int idx = tid * 8 + i * 2048;
            uint4 uh = *(const uint4*)(qh + idx);
            uint4 ul = *(const uint4*)(ql + idx);
            const __nv_bfloat16* ph = (const __nv_bfloat16*)&uh;
            const __nv_bfloat16* pl = (const __nv_bfloat16*)&ul;
            float4 f0, f1;
            f0.x = __bfloat162float(ph[0]) + __bfloat162float(pl[0]);
            f0.y = __bfloat162float(ph[1]) + __bfloat162float(pl[1]);
            f0.z = __bfloat162float(ph[2]) + __bfloat162float(pl[2]);
            f0.w = __bfloat162float(ph[3]) + __bfloat162float(pl[3]);
            f1.x = __bfloat162float(ph[4]) + __bfloat162float(pl[4]);
            f1.y = __bfloat162float(ph[5]) + __bfloat162float(pl[5]);
            f1.z = __bfloat162float(ph[6]) + __bfloat162float(pl[6]);
            f1.w = __bfloat162float(ph[7]) + __bfloat162float(pl[7]);
            *(float4*)&s_qt[idx]     = f0;
            *(float4*)&s_qt[idx + 4] = f1;
        }
    }
    __syncthreads();

    // ---- phase 1: scores via packed f32x2 FMA ----
    {
        const int hg    = (w >> 2) * 4;
        const int mrow0 = (w & 3) * 16;
        const float* kb = k + (long)b * NM * NHID + (long)mrow0 * NHID;
        #pragma unroll 1
        for (int mg = 0; mg < 16; mg += 4) {
            uint64_t acc2[4][4];
            #pragma unroll
            for (int mi = 0; mi < 4; mi++)
                #pragma unroll
                for (int hh = 0; hh < 4; hh++) acc2[mi][hh] = 0ULL;

            #pragma unroll 4
            for (int jb = 0; jb < 8; jb++) {
                const int j = jb * 128 + lane * 4;
                float4 kf[4];
                #pragma unroll
                for (int mi = 0; mi < 4; mi++)
                    kf[mi] = *(const float4*)&kb[(long)(mg + mi) * NHID + j];
                uint64_t q01[4], q23[4];
                #pragma unroll
                for (int hh = 0; hh < 4; hh++) {
                    const float4 qf = *(const float4*)&s_qt[(hg + hh) * NHID + j];
                    q01[hh] = f2u(qf.x, qf.y);
                    q23[hh] = f2u(qf.z, qf.w);
                }
                #pragma unroll
                for (int mi = 0; mi < 4; mi++) {
                    const uint64_t k01 = f2u(kf[mi].x, kf[mi].y);
                    const uint64_t k23 = f2u(kf[mi].z, kf[mi].w);
                    #pragma unroll
                    for (int hh = 0; hh < 4; hh++) {
                        ffma2(acc2[mi][hh], k01, q01[hh]);
                        ffma2(acc2[mi][hh], k23, q23[hh]);
                    }
                }
            }
            #pragma unroll
            for (int mi = 0; mi < 4; mi++)
                #pragma unroll
                for (int hh = 0; hh < 4; hh++) {
                    const float2 t = u2f(acc2[mi][hh]);
                    float s = t.x + t.y;
                    s += __shfl_xor_sync(0xffffffffu, s, 16);
                    s += __shfl_xor_sync(0xffffffffu, s, 8);
                    s += __shfl_xor_sync(0xffffffffu, s, 4);
                    s += __shfl_xor_sync(0xffffffffu, s, 2);
                    s += __shfl_xor_sync(0xffffffffu, s, 1);
                    if (lane == 0) s_p[hg + hh][mrow0 + mg + mi] = s;
                }
        }
    }
    __syncthreads();

    // ---- softmax: warp w handles head w ----
    {
        float s0 = s_p[w][lane];
        float s1 = s_p[w][lane + 32];
        float mx = fmaxf(s0, s1);
        #pragma unroll
        for (int o = 16; o > 0; o >>= 1)
            mx = fmaxf(mx, __shfl_xor_sync(0xffffffffu, mx, o));
        float e0 = expf(s0 - mx);
        float e1 = expf(s1 - mx);
        float sum = e0 + e1;
        #pragma unroll
        for (int o = 16; o > 0; o >>= 1)
            sum += __shfl_xor_sync(0xffffffffu, sum, o);
        const float inv = 1.f / sum;
        s_p[w][lane]      = e0 * inv;
        s_p[w][lane + 32] = e1 * inv;
    }
    __syncthreads();

    // ---- phase 2: y via packed f32x2 FMA ----
    {
        const int j = w * 128 + lane * 4;
        const float* vb = v + (long)b * NM * NHID;
        uint64_t axy[NH], azw[NH];
        #pragma unroll
        for (int hh = 0; hh < NH; hh++) { axy[hh] = 0ULL; azw[hh] = 0ULL; }

        #pragma unroll 2
        for (int m = 0; m < NM; m += 4) {
            float4 vf[4];
            #pragma unroll
            for (int mi = 0; mi < 4; mi++)
                vf[mi] = *(const float4*)&vb[(long)(m + mi) * NHID + j];
            uint64_t vxy[4], vzw[4];
            #pragma unroll
            for (int mi = 0; mi < 4; mi++) {
                vxy[mi] = f2u(vf[mi].x, vf[mi].y);
                vzw[mi] = f2u(vf[mi].z, vf[mi].w);
            }
            #pragma unroll
            for (int hh = 0; hh < NH; hh++) {
                const float4 pa = *(const float4*)&s_p[hh][m];
                const uint64_t p0 = f2u(pa.x, pa.x);
                const uint64_t p1 = f2u(pa.y, pa.y);
                const uint64_t p2 = f2u(pa.z, pa.z);
                const uint64_t p3 = f2u(pa.w, pa.w);
                ffma2(axy[hh], vxy[0], p0); ffma2(azw[hh], vzw[0], p0);
                ffma2(axy[hh], vxy[1], p1); ffma2(azw[hh], vzw[1], p1);
                ffma2(axy[hh], vxy[2], p2); ffma2(azw[hh], vzw[2], p2);
                ffma2(axy[hh], vxy[3], p3); ffma2(azw[hh], vzw[3], p3);
            }
        }
        const long yb = (long)b * (NH * NHID);
        #pragma unroll
        for (int hh = 0; hh < NH; hh++) {
            const float2 txy = u2f(axy[hh]);
            const float2 tzw = u2f(azw[hh]);
            __nv_bfloat16 h0, l0, h1, l1, h2, l2, h3, l3;
            split1(txy.x, h0, l0); split1(txy.y, h1, l1);
            split1(tzw.x, h2, l2); split1(tzw.y, h3, l3);
            uint2 uh, ul;
            uh.x = pack2(h0, h1); uh.y = pack2(h2, h3);
            ul.x = pack2(l0, l1); ul.y = pack2(l2, l3);
            *(uint2*)(yhi + yb + hh * NHID + j) = uh;
            *(uint2*)(ylo + yb + hh * NHID + j) = ul;
        }
    }
}

// ---------------------------------------------------------------------------
// Launch (R4-exact order)
// ---------------------------------------------------------------------------
extern "C" void kernel_launch(void* const* d_in, const int* in_sizes, int n_in,
                              void* d_out, int out_size)
{
    const float* q  = (const float*)d_in[0];
    const float* k  = (const float*)d_in[1];
    const float* v  = (const float*)d_in[2];
    const float* Wq = (const float*)d_in[3];
    const float* Wk = (const float*)d_in[4];
    const float* Wv = (const float*)d_in[5];
    const float* Wb = (const float*)d_in[6];
    const float* Wo = (const float*)d_in[7];
    const float* bo = (const float*)d_in[8];
    float* out = (float*)d_out;

    __nv_bfloat16 *qs_hi, *qs_lo, *Wq_hi, *Wq_lo, *Wb_hi, *Wb_lo;
    __nv_bfloat16 *Wkt_hi, *Wkt_lo, *Wv_hi, *Wv_lo, *Wo_hi, *Wo_lo;
    __nv_bfloat16 *qp_hi, *qp_lo, *qb_hi, *qb_lo, *qt_hi, *qt_lo;
    __nv_bfloat16 *y_hi, *y_lo, *x_hi, *x_lo;
    cudaGetSymbolAddress((void**)&qs_hi, g_qs_hi);   cudaGetSymbolAddress((void**)&qs_lo, g_qs_lo);
    cudaGetSymbolAddress((void**)&Wq_hi, g_Wq_hi);   cudaGetSymbolAddress((void**)&Wq_lo, g_Wq_lo);
    cudaGetSymbolAddress((void**)&Wb_hi, g_Wb_hi);   cudaGetSymbolAddress((void**)&Wb_lo, g_Wb_lo);
    cudaGetSymbolAddress((void**)&Wkt_hi, g_Wkt_hi); cudaGetSymbolAddress((void**)&Wkt_lo, g_Wkt_lo);
    cudaGetSymbolAddress((void**)&Wv_hi, g_Wv_hi);   cudaGetSymbolAddress((void**)&Wv_lo, g_Wv_lo);
    cudaGetSymbolAddress((void**)&Wo_hi, g_Wo_hi);   cudaGetSymbolAddress((void**)&Wo_lo, g_Wo_lo);
    cudaGetSymbolAddress((void**)&qp_hi, g_qp_hi);   cudaGetSymbolAddress((void**)&qp_lo, g_qp_lo);
    cudaGetSymbolAddress((void**)&qb_hi, g_qb_hi);   cudaGetSymbolAddress((void**)&qb_lo, g_qb_lo);
    cudaGetSymbolAddress((void**)&qt_hi, g_qt_hi);   cudaGetSymbolAddress((void**)&qt_lo, g_qt_lo);
    cudaGetSymbolAddress((void**)&y_hi,  g_y_hi);    cudaGetSymbolAddress((void**)&y_lo,  g_y_lo);
    cudaGetSymbolAddress((void**)&x_hi,  g_x_hi);    cudaGetSymbolAddress((void**)&x_lo,  g_x_lo);

    cudaFuncSetAttribute(gemm_ldsm, cudaFuncAttributeMaxDynamicSharedMemorySize, GEMM_SMEM);

    dim3 blk(256);

    // conversions (R4-exact)
    split_f32<<<(NB * NHID / 4 + 255) / 256, blk>>>(q, qs_hi, qs_lo, NB * NHID / 4);
    split_f32<<<(NHID * NHID / 4 + 255) / 256, blk>>>(Wq, Wq_hi, Wq_lo, NHID * NHID / 4);
    split_f32<<<(ND * ND / 4 + 255) / 256, blk>>>(Wb, Wb_hi, Wb_lo, ND * ND / 4);
    tsplit_wk<<<dim3(NHID / 32, ND / 32, NH), blk>>>(Wk, Wkt_hi, Wkt_lo);
    split_f32<<<(NHID * NHID / 4 + 255) / 256, blk>>>(Wv, Wv_hi, Wv_lo, NHID * NHID / 4);

    // G1: qp = q @ Wq^T            M=2048 N=1024 K=1024
    gemm_ldsm<<<dim3(16, 8, 1), blk, GEMM_SMEM>>>(
        qs_hi, qs_lo, NHID, 0, Wq_hi, Wq_lo, NHID, 0,
        nullptr, qp_hi, qp_lo, NHID, 0, NHID, nullptr);
    // G2: qb_h = qp_h @ Wb^T       M=2048 N=128 K=128 (per head)
    gemm_ldsm<<<dim3(16, 1, 8), blk, GEMM_SMEM>>>(
        qp_hi, qp_lo, NHID, ND, Wb_hi, Wb_lo, ND, 0,
        nullptr, qb_hi, qb_lo, NHID, ND, ND, nullptr);
    // G3: qt_h = qb_h @ Wkt_h^T    M=2048 N=1024 K=128 (per head)
    gemm_ldsm<<<dim3(16, 8, 8), blk, GEMM_SMEM>>>(
        qb_hi, qb_lo, NHID, ND, Wkt_hi, Wkt_lo, ND, (long)NHID * ND,
        nullptr, qt_hi, qt_lo, NH * NHID, NHID, ND, nullptr);
    // attention
    attn_stream<<<NB, blk>>>(qt_hi, qt_lo, k, v, y_hi, y_lo);
    split_f32<<<(NHID * NHID / 4 + 255) / 256, blk>>>(Wo, Wo_hi, Wo_lo, NHID * NHID / 4);
    // G4: x_h = y_h @ Wv_h^T       M=2048 N=128 K=1024 (per head)
    gemm_ldsm<<<dim3(16, 1, 8), blk, GEMM_SMEM>>>(
        y_hi, y_lo, NH * NHID, NHID, Wv_hi, Wv_lo, NHID, (long)ND * NHID,
        nullptr, x_hi, x_lo, NHID, ND, NHID, nullptr);
    // G5: out = x @ Wo^T + bo      M=2048 N=1024 K=1024
    gemm_ldsm<<<dim3(16, 8, 1), blk, GEMM_SMEM>>>(
        x_hi, x_lo, NHID, 0, Wo_hi, Wo_lo, NHID, 0,
        out, nullptr, nullptr, NHID, 0, NHID, bo);
}

// round 12
// speedup vs baseline: 1.3952x; 1.3952x over previous
#include <cuda_runtime.h>
#include <cuda_bf16.h>
#include <cstdint>
#include <math.h>

// Problem constants
#define NB   2048
#define NM   64
#define NHID 1024
#define NH   8
#define ND   128

// ---------------------------------------------------------------------------
// Device scratch (allocation-free rule): bf16 hi/lo planes
// ---------------------------------------------------------------------------
__device__ __align__(256) __nv_bfloat16 g_qs_hi [NB * NHID];
__device__ __align__(256) __nv_bfloat16 g_qs_lo [NB * NHID];
__device__ __align__(256) __nv_bfloat16 g_Wq_hi [NHID * NHID];
__device__ __align__(256) __nv_bfloat16 g_Wq_lo [NHID * NHID];
__device__ __align__(256) __nv_bfloat16 g_Wb_hi [ND * ND];
__device__ __align__(256) __nv_bfloat16 g_Wb_lo [ND * ND];
__device__ __align__(256) __nv_bfloat16 g_Wkt_hi[NH * NHID * ND];  // [h][j][d]
__device__ __align__(256) __nv_bfloat16 g_Wkt_lo[NH * NHID * ND];
__device__ __align__(256) __nv_bfloat16 g_Wv_hi [NHID * NHID];
__device__ __align__(256) __nv_bfloat16 g_Wv_lo [NHID * NHID];
__device__ __align__(256) __nv_bfloat16 g_Wo_hi [NHID * NHID];
__device__ __align__(256) __nv_bfloat16 g_Wo_lo [NHID * NHID];
__device__ __align__(256) __nv_bfloat16 g_qp_hi [NB * NHID];
__device__ __align__(256) __nv_bfloat16 g_qp_lo [NB * NHID];
__device__ __align__(256) __nv_bfloat16 g_qb_hi [NB * NHID];
__device__ __align__(256) __nv_bfloat16 g_qb_lo [NB * NHID];
__device__ __align__(256) __nv_bfloat16 g_qt_hi [NB * NH * NHID];
__device__ __align__(256) __nv_bfloat16 g_qt_lo [NB * NH * NHID];
__device__ __align__(256) __nv_bfloat16 g_y_hi  [NB * NH * NHID];
__device__ __align__(256) __nv_bfloat16 g_y_lo  [NB * NH * NHID];
__device__ __align__(256) __nv_bfloat16 g_x_hi  [NB * NHID];
__device__ __align__(256) __nv_bfloat16 g_x_lo  [NB * NHID];

// ---------------------------------------------------------------------------
// Helpers
// ---------------------------------------------------------------------------
__device__ __forceinline__ uint32_t pack2(__nv_bfloat16 a, __nv_bfloat16 b) {
    uint16_t ua = *reinterpret_cast<uint16_t*>(&a);
    uint16_t ub = *reinterpret_cast<uint16_t*>(&b);
    return (uint32_t)ua | ((uint32_t)ub << 16);
}

__device__ __forceinline__ void split1(float v, __nv_bfloat16& h, __nv_bfloat16& l) {
    h = __float2bfloat16(v);
    l = __float2bfloat16(v - __bfloat162float(h));
}

__device__ __forceinline__ void cpa16s(uint32_t s, const void* g) {
    asm volatile("cp.async.cg.shared.global [%0], [%1], 16;\n" :: "r"(s), "l"(g));
}
__device__ __forceinline__ void cpa_commit() {
    asm volatile("cp.async.commit_group;\n");
}
template <int N>
__device__ __forceinline__ void cpa_wait() {
    asm volatile("cp.async.wait_group %0;\n" :: "n"(N));
}

__device__ __forceinline__ void mma_bf16(float* c, const uint32_t* a,
                                         uint32_t b0, uint32_t b1) {
    asm volatile(
        "mma.sync.aligned.m16n8k16.row.col.f32.bf16.bf16.f32 "
        "{%0,%1,%2,%3}, {%4,%5,%6,%7}, {%8,%9}, {%0,%1,%2,%3};\n"
        : "+f"(c[0]), "+f"(c[1]), "+f"(c[2]), "+f"(c[3])
        : "r"(a[0]), "r"(a[1]), "r"(a[2]), "r"(a[3]),
          "r"(b0), "r"(b1));
}

__device__ __forceinline__ void ldsm4(uint32_t* r, uint32_t addr) {
    asm volatile(
        "ldmatrix.sync.aligned.m8n8.x4.shared.b16 {%0,%1,%2,%3}, [%4];\n"
        : "=r"(r[0]), "=r"(r[1]), "=r"(r[2]), "=r"(r[3])
        : "r"(addr));
}

// ---------------------------------------------------------------------------
// Conversion kernels (R4-exact)
// ---------------------------------------------------------------------------
__global__ void __launch_bounds__(256) split_f32(
    const float* __restrict__ src, __nv_bfloat16* __restrict__ hi,
    __nv_bfloat16* __restrict__ lo, int n4)
{
    int i = blockIdx.x * 256 + threadIdx.x;
    if (i >= n4) return;
    float4 f = ((const float4*)src)[i];
    float vv[4] = {f.x, f.y, f.z, f.w};
    __nv_bfloat16 h[4], l[4];
    #pragma unroll
    for (int j = 0; j < 4; j++) split1(vv[j], h[j], l[j]);
    uint2 uh, ul;
    uh.x = pack2(h[0], h[1]); uh.y = pack2(h[2], h[3]);
    ul.x = pack2(l[0], l[1]); ul.y = pack2(l[2], l[3]);
    ((uint2*)hi)[i] = uh;
    ((uint2*)lo)[i] = ul;
}

// Transpose + split Wk: out[h][j][d] = Wk[h*ND + d][j]
__global__ void __launch_bounds__(256) tsplit_wk(
    const float* __restrict__ Wk, __nv_bfloat16* __restrict__ hi,
    __nv_bfloat16* __restrict__ lo)
{
    __shared__ float t[32][33];
    const int h  = blockIdx.z;
    const int d0 = blockIdx.y * 32;
    const int j0 = blockIdx.x * 32;
    const int tx = threadIdx.x & 31;
    const int ty = threadIdx.x >> 5;
    #pragma unroll
    for (int r = ty; r < 32; r += 8)
        t[r][tx] = Wk[(long)(h * ND + d0 + r) * NHID + j0 + tx];
    __syncthreads();
    #pragma unroll
    for (int r = ty; r < 32; r += 8) {
        float v = t[tx][r];
        __nv_bfloat16 hb, lb;
        split1(v, hb, lb);
        long o = (long)h * NHID * ND + (long)(j0 + r) * ND + d0 + tx;
        hi[o] = hb;
        lo[o] = lb;
    }
}

// ---------------------------------------------------------------------------
// GEMM v3 (R4-exact): C[M,N] = A[M,K] @ B[N,K]^T, split-bf16 x3, ldmatrix.
// Tiles BM=128, BN=128, BK=32. 256 threads = 8 warps (2 M x 4 N), warp 64x32.
// 2-stage cp.async double buffering. smem rows: SK=40 bf16 (80B).
// ---------------------------------------------------------------------------
#define SK 40
#define PLANE_B (128 * SK * 2)        // 10240 bytes per plane
#define STAGE_B (4 * PLANE_B)         // 40960 bytes per stage
#define GEMM_SMEM (2 * STAGE_B)       // 81920 bytes

__device__ __forceinline__ void gemm_issue(
    uint32_t sb,
    const __nv_bfloat16* __restrict__ Ah, const __nv_bfloat16* __restrict__ Al, int lda,
    const __nv_bfloat16* __restrict__ Bh, const __nv_bfloat16* __restrict__ Bl, int ldb,
    int m0, int n0, int kk, int tid)
{
    #pragma unroll
    for (int i = 0; i < 2; i++) {
        const int c   = tid + i * 256;        // 0..511
        const int row = c >> 2;
        const int col = c & 3;                // 16B chunk within 64B row
        const uint32_t so = row * 80 + col * 16;
        const long ga = (long)(m0 + row) * lda + kk + col * 8;
        cpa16s(sb + so,               Ah + ga);
        cpa16s(sb + PLANE_B + so,     Al + ga);
        const long gb = (long)(n0 + row) * ldb + kk + col * 8;
        cpa16s(sb + 2 * PLANE_B + so, Bh + gb);
        cpa16s(sb + 3 * PLANE_B + so, Bl + gb);
    }
    cpa_commit();
}

__global__ void __launch_bounds__(256) gemm_ldsm(
    const __nv_bfloat16* __restrict__ Ah, const __nv_bfloat16* __restrict__ Al,
    int lda, long strideAh,
    const __nv_bfloat16* __restrict__ Bh, const __nv_bfloat16* __restrict__ Bl,
    int ldb, long strideBh,
    float* __restrict__ Cf, __nv_bfloat16* __restrict__ Chi, __nv_bfloat16* __restrict__ Clo,
    int ldc, long strideCh,
    int K, const float* __restrict__ bias)
{
    extern __shared__ __align__(16) char dsm[];

    const int h = blockIdx.z;
    Ah += (long)h * strideAh;  Al += (long)h * strideAh;
    Bh += (long)h * strideBh;  Bl += (long)h * strideBh;
    if (Cf)  Cf  += (long)h * strideCh;
    if (Chi) { Chi += (long)h * strideCh; Clo += (long)h * strideCh; }

    const int m0 = blockIdx.x * 128;
    const int n0 = blockIdx.y * 128;
    const int tid  = threadIdx.x;
    const int lane = tid & 31;
    const int warp = tid >> 5;
    const int wm = warp & 1;    // 2 warps along M (64 rows each)
    const int wn = warp >> 1;   // 4 warps along N (32 cols each)

    const uint32_t sbase = (uint32_t)__cvta_generic_to_shared(dsm);

    float acc[4][4][4];
    #pragma unroll
    for (int i = 0; i < 4; i++)
        #pragma unroll
        for (int j = 0; j < 4; j++)
            #pragma unroll
            for (int l = 0; l < 4; l++) acc[i][j][l] = 0.f;

    const int nk = K >> 5;

    gemm_issue(sbase, Ah, Al, lda, Bh, Bl, ldb, m0, n0, 0, tid);

    const int lg = lane >> 3;
    const int lr = lane & 7;
    const uint32_t a_row_off = ((lg & 1) * 8 + lr) * 80 + (lg >> 1) * 16;

    for (int ks = 0; ks < nk; ks++) {
        if (ks + 1 < nk) {
            gemm_issue(sbase + ((ks + 1) & 1) * STAGE_B, Ah, Al, lda, Bh, Bl, ldb,
                       m0, n0, (ks + 1) << 5, tid);
            cpa_wait<1>();
        } else {
            cpa_wait<0>();
        }
        __syncthreads();

        const uint32_t st = sbase + (ks & 1) * STAGE_B;
        const uint32_t sAhi = st;
        const uint32_t sAlo = st + PLANE_B;
        const uint32_t sBhi = st + 2 * PLANE_B;
        const uint32_t sBlo = st + 3 * PLANE_B;

        #pragma unroll
        for (int kf = 0; kf < 2; kf++) {
            const uint32_t kb2 = kf * 32;   // byte offset of k16 slice
            uint32_t ahi[4][4], alo[4][4];
            uint32_t bhi[4][2], blo[4][2];

            #pragma unroll
            for (int mt = 0; mt < 4; mt++) {
                const uint32_t ro = (wm * 64 + mt * 16) * 80 + a_row_off + kb2;
                ldsm4(ahi[mt], sAhi + ro);
                ldsm4(alo[mt], sAlo + ro);
            }
            #pragma unroll
            for (int pt = 0; pt < 2; pt++) {
                const uint32_t ro = (wn * 32 + pt * 16) * 80 + a_row_off + kb2;
                uint32_t rh[4], rl[4];
                ldsm4(rh, sBhi + ro);
                ldsm4(rl, sBlo + ro);
                bhi[pt * 2][0]     = rh[0]; bhi[pt * 2][1]     = rh[2];
                bhi[pt * 2 + 1][0] = rh[1]; bhi[pt * 2 + 1][1] = rh[3];
                blo[pt * 2][0]     = rl[0]; blo[pt * 2][1]     = rl[2];
                blo[pt * 2 + 1][0] = rl[1]; blo[pt * 2 + 1][1] = rl[3];
            }

            #pragma unroll
            for (int mt = 0; mt < 4; mt++)
                #pragma unroll
                for (int nt = 0; nt < 4; nt++) {
                    mma_bf16(acc[mt][nt], ahi[mt], bhi[nt][0], bhi[nt][1]);  // hi*hi
                    mma_bf16(acc[mt][nt], ahi[mt], blo[nt][0], blo[nt][1]);  // hi*lo
                    mma_bf16(acc[mt][nt], alo[mt], bhi[nt][0], bhi[nt][1]);  // lo*hi
                }
        }
        __syncthreads();
    }

    // ---- epilogue ----
    const int g  = lane >> 2;
    const int tc = (lane & 3) * 2;
    #pragma unroll
    for (int mt = 0; mt < 4; mt++)
        #pragma unroll
        for (int nt = 0; nt < 4; nt++) {
            const int r = m0 + wm * 64 + mt * 16 + g;
            const int c = n0 + wn * 32 + nt * 8 + tc;
            float b0 = 0.f, b1 = 0.f;
            if (bias) { b0 = bias[c]; b1 = bias[c + 1]; }
            float v00 = acc[mt][nt][0] + b0, v01 = acc[mt][nt][1] + b1;
            float v10 = acc[mt][nt][2] + b0, v11 = acc[mt][nt][3] + b1;
            if (Cf) {
                *(float2*)(Cf + (long)r * ldc + c)       = make_float2(v00, v01);
                *(float2*)(Cf + (long)(r + 8) * ldc + c) = make_float2(v10, v11);
            } else {
                __nv_bfloat16 h0, l0, h1, l1;
                split1(v00, h0, l0); split1(v01, h1, l1);
                *(uint32_t*)(Chi + (long)r * ldc + c) = pack2(h0, h1);
                *(uint32_t*)(Clo + (long)r * ldc + c) = pack2(l0, l1);
                split1(v10, h0, l0); split1(v11, h1, l1);
                *(uint32_t*)(Chi + (long)(r + 8) * ldc + c) = pack2(h0, h1);
                *(uint32_t*)(Clo + (long)(r + 8) * ldc + c) = pack2(l0, l1);
            }
        }
}

// ---------------------------------------------------------------------------
// Streaming attention (R4-exact): one CTA per batch element, occ 2.
// ---------------------------------------------------------------------------
__global__ void __launch_bounds__(256, 2) attn_stream(
    const __nv_bfloat16* __restrict__ qthi, const __nv_bfloat16* __restrict__ qtlo,
    const float* __restrict__ k, const float* __restrict__ v,
    __nv_bfloat16* __restrict__ yhi, __nv_bfloat16* __restrict__ ylo)
{
    __shared__ __align__(16) float s_qt[NH * NHID];
    __shared__ __align__(16) float s_p[NH][NM];

    const int b    = blockIdx.x;
    const int tid  = threadIdx.x;
    const int lane = tid & 31;
    const int w    = tid >> 5;

    {
        const __nv_bfloat16* qh = qthi + (long)b * (NH * NHID);
        const __nv_bfloat16* ql = qtlo + (long)b * (NH * NHID);
        #pragma unroll
        for (int i = 0; i < 4; i++) {
            const int idx = tid * 8 + i * 2048;
            uint4 uh = *(const uint4*)(qh + idx);
            uint4 ul = *(const uint4*)(ql + idx);
            const __nv_bfloat16* ph = (const __nv_bfloat16*)&uh;
            const __nv_bfloat16* pl = (const __nv_bfloat16*)&ul;
            float4 f0, f1;
            f0.x = __bfloat162float(ph[0]) + __bfloat162float(pl[0]);
            f0.y = __bfloat162float(ph[1]) + __bfloat162float(pl[1]);
            f0.z = __bfloat162float(ph[2]) + __bfloat162float(pl[2]);
            f0.w = __bfloat162float(ph[3]) + __bfloat162float(pl[3]);
            f1.x = __bfloat162float(ph[4]) + __bfloat162float(pl[4]);
            f1.y = __bfloat162float(ph[5]) + __bfloat162float(pl[5]);
            f1.z = __bfloat162float(ph[6]) + __bfloat162float(pl[6]);
            f1.w = __bfloat162float(ph[7]) + __bfloat162float(pl[7]);
            *(float4*)&s_qt[idx]     = f0;
            *(float4*)&s_qt[idx + 4] = f1;
        }
    }
    __syncthreads();

    {
        const int hg    = (w >> 2) * 4;
        const int mrow0 = (w & 3) * 16;
        const float* kb = k + (long)b * NM * NHID + (long)mrow0 * NHID;
        #pragma unroll 1
        for (int mg = 0; mg < 16; mg += 4) {
            float acc[4][4];
            #pragma unroll
            for (int mi = 0; mi < 4; mi++)
                #pragma unroll
                for (int hh = 0; hh < 4; hh++) acc[mi][hh] = 0.f;

            #pragma unroll 4
            for (int jb = 0; jb < 8; jb++) {
                const int j = jb * 128 + lane * 4;
                float4 kf[4];
                #pragma unroll
                for (int mi = 0; mi < 4; mi++)
                    kf[mi] = *(const float4*)&kb[(long)(mg + mi) * NHID + j];
                float4 qf[4];
                #pragma unroll
                for (int hh = 0; hh < 4; hh++)
                    qf[hh] = *(const float4*)&s_qt[(hg + hh) * NHID + j];
                #pragma unroll
                for (int mi = 0; mi < 4; mi++)
                    #pragma unroll
                    for (int hh = 0; hh < 4; hh++) {
                        acc[mi][hh] += kf[mi].x * qf[hh].x;
                        acc[mi][hh] += kf[mi].y * qf[hh].y;
                        acc[mi][hh] += kf[mi].z * qf[hh].z;
                        acc[mi][hh] += kf[mi].w * qf[hh].w;
                    }
            }
            #pragma unroll
            for (int mi = 0; mi < 4; mi++)
                #pragma unroll
                for (int hh = 0; hh < 4; hh++) {
                    float s = acc[mi][hh];
                    s += __shfl_xor_sync(0xffffffffu, s, 16);
                    s += __shfl_xor_sync(0xffffffffu, s, 8);
                    s += __shfl_xor_sync(0xffffffffu, s, 4);
                    s += __shfl_xor_sync(0xffffffffu, s, 2);
                    s += __shfl_xor_sync(0xffffffffu, s, 1);
                    if (lane == 0) s_p[hg + hh][mrow0 + mg + mi] = s;
                }
        }
    }
    __syncthreads();

    {
        float s0 = s_p[w][lane];
        float s1 = s_p[w][lane + 32];
        float mx = fmaxf(s0, s1);
        #pragma unroll
        for (int o = 16; o > 0; o >>= 1)
            mx = fmaxf(mx, __shfl_xor_sync(0xffffffffu, mx, o));
        float e0 = expf(s0 - mx);
        float e1 = expf(s1 - mx);
        float sum = e0 + e1;
        #pragma unroll
        for (int o = 16; o > 0; o >>= 1)
            sum += __shfl_xor_sync(0xffffffffu, sum, o);
        const float inv = 1.f / sum;
        s_p[w][lane]      = e0 * inv;
        s_p[w][lane + 32] = e1 * inv;
    }
    __syncthreads();

    {
        const int j = w * 128 + lane * 4;
        const float* vb = v + (long)b * NM * NHID;
        float4 acc[NH];
        #pragma unroll
        for (int hh = 0; hh < NH; hh++) acc[hh] = make_float4(0.f, 0.f, 0.f, 0.f);

        #pragma unroll 2
        for (int m = 0; m < NM; m += 4) {
            float4 vf[4];
            #pragma unroll
            for (int mi = 0; mi < 4; mi++)
                vf[mi] = *(const float4*)&vb[(long)(m + mi) * NHID + j];
            #pragma unroll
            for (int hh = 0; hh < NH; hh++) {
                const float4 pa = *(const float4*)&s_p[hh][m];
                acc[hh].x += pa.x * vf[0].x + pa.y * vf[1].x + pa.z * vf[2].x + pa.w * vf[3].x;
                acc[hh].y += pa.x * vf[0].y + pa.y * vf[1].y + pa.z * vf[2].y + pa.w * vf[3].y;
                acc[hh].z += pa.x * vf[0].z + pa.y * vf[1].z + pa.z * vf[2].z + pa.w * vf[3].z;
                acc[hh].w += pa.x * vf[0].w + pa.y * vf[1].w + pa.z * vf[2].w + pa.w * vf[3].w;
            }
        }
        const long yb = (long)b * (NH * NHID);
        #pragma unroll
        for (int hh = 0; hh < NH; hh++) {
            const float4 a = acc[hh];
            __nv_bfloat16 h0, l0, h1, l1, h2, l2, h3, l3;
            split1(a.x, h0, l0); split1(a.y, h1, l1);
            split1(a.z, h2, l2); split1(a.w, h3, l3);
            uint2 uh, ul;
            uh.x = pack2(h0, h1); uh.y = pack2(h2, h3);
            ul.x = pack2(l0, l1); ul.y = pack2(l2, l3);
            *(uint2*)(yhi + yb + hh * NHID + j) = uh;
            *(uint2*)(ylo + yb + hh * NHID + j) = ul;
        }
    }
}

// ---------------------------------------------------------------------------
// Launch (R4-exact order)
// ---------------------------------------------------------------------------
extern "C" void kernel_launch(void* const* d_in, const int* in_sizes, int n_in,
                              void* d_out, int out_size)
{
    const float* q  = (const float*)d_in[0];
    const float* k  = (const float*)d_in[1];
    const float* v  = (const float*)d_in[2];
    const float* Wq = (const float*)d_in[3];
    const float* Wk = (const float*)d_in[4];
    const float* Wv = (const float*)d_in[5];
    const float* Wb = (const float*)d_in[6];
    const float* Wo = (const float*)d_in[7];
    const float* bo = (const float*)d_in[8];
    float* out = (float*)d_out;

    __nv_bfloat16 *qs_hi, *qs_lo, *Wq_hi, *Wq_lo, *Wb_hi, *Wb_lo;
    __nv_bfloat16 *Wkt_hi, *Wkt_lo, *Wv_hi, *Wv_lo, *Wo_hi, *Wo_lo;
    __nv_bfloat16 *qp_hi, *qp_lo, *qb_hi, *qb_lo, *qt_hi, *qt_lo;
    __nv_bfloat16 *y_hi, *y_lo, *x_hi, *x_lo;
    cudaGetSymbolAddress((void**)&qs_hi, g_qs_hi);   cudaGetSymbolAddress((void**)&qs_lo, g_qs_lo);
    cudaGetSymbolAddress((void**)&Wq_hi, g_Wq_hi);   cudaGetSymbolAddress((void**)&Wq_lo, g_Wq_lo);
    cudaGetSymbolAddress((void**)&Wb_hi, g_Wb_hi);   cudaGetSymbolAddress((void**)&Wb_lo, g_Wb_lo);
    cudaGetSymbolAddress((void**)&Wkt_hi, g_Wkt_hi); cudaGetSymbolAddress((void**)&Wkt_lo, g_Wkt_lo);
    cudaGetSymbolAddress((void**)&Wv_hi, g_Wv_hi);   cudaGetSymbolAddress((void**)&Wv_lo, g_Wv_lo);
    cudaGetSymbolAddress((void**)&Wo_hi, g_Wo_hi);   cudaGetSymbolAddress((void**)&Wo_lo, g_Wo_lo);
    cudaGetSymbolAddress((void**)&qp_hi, g_qp_hi);   cudaGetSymbolAddress((void**)&qp_lo, g_qp_lo);
    cudaGetSymbolAddress((void**)&qb_hi, g_qb_hi);   cudaGetSymbolAddress((void**)&qb_lo, g_qb_lo);
    cudaGetSymbolAddress((void**)&qt_hi, g_qt_hi);   cudaGetSymbolAddress((void**)&qt_lo, g_qt_lo);
    cudaGetSymbolAddress((void**)&y_hi,  g_y_hi);    cudaGetSymbolAddress((void**)&y_lo,  g_y_lo);
    cudaGetSymbolAddress((void**)&x_hi,  g_x_hi);    cudaGetSymbolAddress((void**)&x_lo,  g_x_lo);

    cudaFuncSetAttribute(gemm_ldsm, cudaFuncAttributeMaxDynamicSharedMemorySize, GEMM_SMEM);

    dim3 blk(256);

    // conversions (R4-exact)
    split_f32<<<(NB * NHID / 4 + 255) / 256, blk>>>(q, qs_hi, qs_lo, NB * NHID / 4);
    split_f32<<<(NHID * NHID / 4 + 255) / 256, blk>>>(Wq, Wq_hi, Wq_lo, NHID * NHID / 4);
    split_f32<<<(ND * ND / 4 + 255) / 256, blk>>>(Wb, Wb_hi, Wb_lo, ND * ND / 4);
    tsplit_wk<<<dim3(NHID / 32, ND / 32, NH), blk>>>(Wk, Wkt_hi, Wkt_lo);
    split_f32<<<(NHID * NHID / 4 + 255) / 256, blk>>>(Wv, Wv_hi, Wv_lo, NHID * NHID / 4);

    // G1: qp = q @ Wq^T            M=2048 N=1024 K=1024
    gemm_ldsm<<<dim3(16, 8, 1), blk, GEMM_SMEM>>>(
        qs_hi, qs_lo, NHID, 0, Wq_hi, Wq_lo, NHID, 0,
        nullptr, qp_hi, qp_lo, NHID, 0, NHID, nullptr);
    // G2: qb_h = qp_h @ Wb^T       M=2048 N=128 K=128 (per head)
    gemm_ldsm<<<dim3(16, 1, 8), blk, GEMM_SMEM>>>(
        qp_hi, qp_lo, NHID, ND, Wb_hi, Wb_lo, ND, 0,
        nullptr, qb_hi, qb_lo, NHID, ND, ND, nullptr);
    // G3: qt_h = qb_h @ Wkt_h^T    M=2048 N=1024 K=128 (per head)
    gemm_ldsm<<<dim3(16, 8, 8), blk, GEMM_SMEM>>>(
        qb_hi, qb_lo, NHID, ND, Wkt_hi, Wkt_lo, ND, (long)NHID * ND,
        nullptr, qt_hi, qt_lo, NH * NHID, NHID, ND, nullptr);
    // attention
    attn_stream<<<NB, blk>>>(qt_hi, qt_lo, k, v, y_hi, y_lo);
    split_f32<<<(NHID * NHID / 4 + 255) / 256, blk>>>(Wo, Wo_hi, Wo_lo, NHID * NHID / 4);
    // G4: x_h = y_h @ Wv_h^T       M=2048 N=128 K=1024 (per head)
    gemm_ldsm<<<dim3(16, 1, 8), blk, GEMM_SMEM>>>(
        y_hi, y_lo, NH * NHID, NHID, Wv_hi, Wv_lo, NHID, (long)ND * NHID,
        nullptr, x_hi, x_lo, NHID, ND, NHID, nullptr);
    // G5: out = x @ Wo^T + bo      M=2048 N=1024 K=1024
    gemm_ldsm<<<dim3(16, 8, 1), blk, GEMM_SMEM>>>(
        x_hi, x_lo, NHID, 0, Wo_hi, Wo_lo, NHID, 0,
        out, nullptr, nullptr, NHID, 0, NHID, bo);
}

// round 13
// speedup vs baseline: 1.3959x; 1.0005x over previous
#include <cuda_runtime.h>
#include <cuda_bf16.h>
#include <cstdint>
#include <math.h>

// Problem constants
#define NB   2048
#define NM   64
#define NHID 1024
#define NH   8
#define ND   128

// ---------------------------------------------------------------------------
// Device scratch (allocation-free rule): bf16 hi/lo planes
// ---------------------------------------------------------------------------
__device__ __align__(256) __nv_bfloat16 g_qs_hi [NB * NHID];
__device__ __align__(256) __nv_bfloat16 g_qs_lo [NB * NHID];
__device__ __align__(256) __nv_bfloat16 g_Wq_hi [NHID * NHID];
__device__ __align__(256) __nv_bfloat16 g_Wq_lo [NHID * NHID];
__device__ __align__(256) __nv_bfloat16 g_Wb_hi [ND * ND];
__device__ __align__(256) __nv_bfloat16 g_Wb_lo [ND * ND];
__device__ __align__(256) __nv_bfloat16 g_Wkt_hi[NH * NHID * ND];  // [h][j][d]
__device__ __align__(256) __nv_bfloat16 g_Wkt_lo[NH * NHID * ND];
__device__ __align__(256) __nv_bfloat16 g_Wv_hi [NHID * NHID];
__device__ __align__(256) __nv_bfloat16 g_Wv_lo [NHID * NHID];
__device__ __align__(256) __nv_bfloat16 g_Wo_hi [NHID * NHID];
__device__ __align__(256) __nv_bfloat16 g_Wo_lo [NHID * NHID];
__device__ __align__(256) __nv_bfloat16 g_qp_hi [NB * NHID];
__device__ __align__(256) __nv_bfloat16 g_qp_lo [NB * NHID];
__device__ __align__(256) __nv_bfloat16 g_qb_hi [NB * NHID];
__device__ __align__(256) __nv_bfloat16 g_qb_lo [NB * NHID];
__device__ __align__(256) __nv_bfloat16 g_qt_hi [NB * NH * NHID];
__device__ __align__(256) __nv_bfloat16 g_qt_lo [NB * NH * NHID];
__device__ __align__(256) __nv_bfloat16 g_y_hi  [NB * NH * NHID];
__device__ __align__(256) __nv_bfloat16 g_y_lo  [NB * NH * NHID];
__device__ __align__(256) __nv_bfloat16 g_x_hi  [NB * NHID];
__device__ __align__(256) __nv_bfloat16 g_x_lo  [NB * NHID];

// ---------------------------------------------------------------------------
// Helpers
// ---------------------------------------------------------------------------
__device__ __forceinline__ uint32_t pack2(__nv_bfloat16 a, __nv_bfloat16 b) {
    uint16_t ua = *reinterpret_cast<uint16_t*>(&a);
    uint16_t ub = *reinterpret_cast<uint16_t*>(&b);
    return (uint32_t)ua | ((uint32_t)ub << 16);
}

__device__ __forceinline__ void split1(float v, __nv_bfloat16& h, __nv_bfloat16& l) {
    h = __float2bfloat16(v);
    l = __float2bfloat16(v - __bfloat162float(h));
}

__device__ __forceinline__ void cpa16s(uint32_t s, const void* g) {
    asm volatile("cp.async.cg.shared.global [%0], [%1], 16;\n" :: "r"(s), "l"(g));
}
__device__ __forceinline__ void cpa_commit() {
    asm volatile("cp.async.commit_group;\n");
}
template <int N>
__device__ __forceinline__ void cpa_wait() {
    asm volatile("cp.async.wait_group %0;\n" :: "n"(N));
}

__device__ __forceinline__ void mma_bf16(float* c, const uint32_t* a,
                                         uint32_t b0, uint32_t b1) {
    asm volatile(
        "mma.sync.aligned.m16n8k16.row.col.f32.bf16.bf16.f32 "
        "{%0,%1,%2,%3}, {%4,%5,%6,%7}, {%8,%9}, {%0,%1,%2,%3};\n"
        : "+f"(c[0]), "+f"(c[1]), "+f"(c[2]), "+f"(c[3])
        : "r"(a[0]), "r"(a[1]), "r"(a[2]), "r"(a[3]),
          "r"(b0), "r"(b1));
}

__device__ __forceinline__ void ldsm4(uint32_t* r, uint32_t addr) {
    asm volatile(
        "ldmatrix.sync.aligned.m8n8.x4.shared.b16 {%0,%1,%2,%3}, [%4];\n"
        : "=r"(r[0]), "=r"(r[1]), "=r"(r[2]), "=r"(r[3])
        : "r"(addr));
}

// ---------------------------------------------------------------------------
// Conversion kernels (R4-exact)
// ---------------------------------------------------------------------------
__global__ void __launch_bounds__(256) split_f32(
    const float* __restrict__ src, __nv_bfloat16* __restrict__ hi,
    __nv_bfloat16* __restrict__ lo, int n4)
{
    int i = blockIdx.x * 256 + threadIdx.x;
    if (i >= n4) return;
    float4 f = ((const float4*)src)[i];
    float vv[4] = {f.x, f.y, f.z, f.w};
    __nv_bfloat16 h[4], l[4];
    #pragma unroll
    for (int j = 0; j < 4; j++) split1(vv[j], h[j], l[j]);
    uint2 uh, ul;
    uh.x = pack2(h[0], h[1]); uh.y = pack2(h[2], h[3]);
    ul.x = pack2(l[0], l[1]); ul.y = pack2(l[2], l[3]);
    ((uint2*)hi)[i] = uh;
    ((uint2*)lo)[i] = ul;
}

// Transpose + split Wk: out[h][j][d] = Wk[h*ND + d][j]
__global__ void __launch_bounds__(256) tsplit_wk(
    const float* __restrict__ Wk, __nv_bfloat16* __restrict__ hi,
    __nv_bfloat16* __restrict__ lo)
{
    __shared__ float t[32][33];
    const int h  = blockIdx.z;
    const int d0 = blockIdx.y * 32;
    const int j0 = blockIdx.x * 32;
    const int tx = threadIdx.x & 31;
    const int ty = threadIdx.x >> 5;
    #pragma unroll
    for (int r = ty; r < 32; r += 8)
        t[r][tx] = Wk[(long)(h * ND + d0 + r) * NHID + j0 + tx];
    __syncthreads();
    #pragma unroll
    for (int r = ty; r < 32; r += 8) {
        float v = t[tx][r];
        __nv_bfloat16 hb, lb;
        split1(v, hb, lb);
        long o = (long)h * NHID * ND + (long)(j0 + r) * ND + d0 + tx;
        hi[o] = hb;
        lo[o] = lb;
    }
}

// ---------------------------------------------------------------------------
// GEMM v3 (R4-exact): C[M,N] = A[M,K] @ B[N,K]^T, split-bf16 x3, ldmatrix.
// Tiles BM=128, BN=128, BK=32. 256 threads = 8 warps (2 M x 4 N), warp 64x32.
// 2-stage cp.async double buffering. smem rows: SK=40 bf16 (80B).
// ---------------------------------------------------------------------------
#define SK 40
#define PLANE_B (128 * SK * 2)        // 10240 bytes per plane
#define STAGE_B (4 * PLANE_B)         // 40960 bytes per stage
#define GEMM_SMEM (2 * STAGE_B)       // 81920 bytes

__device__ __forceinline__ void gemm_issue(
    uint32_t sb,
    const __nv_bfloat16* __restrict__ Ah, const __nv_bfloat16* __restrict__ Al, int lda,
    const __nv_bfloat16* __restrict__ Bh, const __nv_bfloat16* __restrict__ Bl, int ldb,
    int m0, int n0, int kk, int tid)
{
    #pragma unroll
    for (int i = 0; i < 2; i++) {
        const int c   = tid + i * 256;        // 0..511
        const int row = c >> 2;
        const int col = c & 3;                // 16B chunk within 64B row
        const uint32_t so = row * 80 + col * 16;
        const long ga = (long)(m0 + row) * lda + kk + col * 8;
        cpa16s(sb + so,               Ah + ga);
        cpa16s(sb + PLANE_B + so,     Al + ga);
        const long gb = (long)(n0 + row) * ldb + kk + col * 8;
        cpa16s(sb + 2 * PLANE_B + so, Bh + gb);
        cpa16s(sb + 3 * PLANE_B + so, Bl + gb);
    }
    cpa_commit();
}

__global__ void __launch_bounds__(256) gemm_ldsm(
    const __nv_bfloat16* __restrict__ Ah, const __nv_bfloat16* __restrict__ Al,
    int lda, long strideAh,
    const __nv_bfloat16* __restrict__ Bh, const __nv_bfloat16* __restrict__ Bl,
    int ldb, long strideBh,
    float* __restrict__ Cf, __nv_bfloat16* __restrict__ Chi, __nv_bfloat16* __restrict__ Clo,
    int ldc, long strideCh,
    int K, const float* __restrict__ bias)
{
    extern __shared__ __align__(16) char dsm[];

    const int h = blockIdx.z;
    Ah += (long)h * strideAh;  Al += (long)h * strideAh;
    Bh += (long)h * strideBh;  Bl += (long)h * strideBh;
    if (Cf)  Cf  += (long)h * strideCh;
    if (Chi) { Chi += (long)h * strideCh; Clo += (long)h * strideCh; }

    const int m0 = blockIdx.x * 128;
    const int n0 = blockIdx.y * 128;
    const int tid  = threadIdx.x;
    const int lane = tid & 31;
    const int warp = tid >> 5;
    const int wm = warp & 1;    // 2 warps along M (64 rows each)
    const int wn = warp >> 1;   // 4 warps along N (32 cols each)

    const uint32_t sbase = (uint32_t)__cvta_generic_to_shared(dsm);

    float acc[4][4][4];
    #pragma unroll
    for (int i = 0; i < 4; i++)
        #pragma unroll
        for (int j = 0; j < 4; j++)
            #pragma unroll
            for (int l = 0; l < 4; l++) acc[i][j][l] = 0.f;

    const int nk = K >> 5;

    gemm_issue(sbase, Ah, Al, lda, Bh, Bl, ldb, m0, n0, 0, tid);

    const int lg = lane >> 3;
    const int lr = lane & 7;
    const uint32_t a_row_off = ((lg & 1) * 8 + lr) * 80 + (lg >> 1) * 16;

    for (int ks = 0; ks < nk; ks++) {
        if (ks + 1 < nk) {
            gemm_issue(sbase + ((ks + 1) & 1) * STAGE_B, Ah, Al, lda, Bh, Bl, ldb,
                       m0, n0, (ks + 1) << 5, tid);
            cpa_wait<1>();
        } else {
            cpa_wait<0>();
        }
        __syncthreads();

        const uint32_t st = sbase + (ks & 1) * STAGE_B;
        const uint32_t sAhi = st;
        const uint32_t sAlo = st + PLANE_B;
        const uint32_t sBhi = st + 2 * PLANE_B;
        const uint32_t sBlo = st + 3 * PLANE_B;

        #pragma unroll
        for (int kf = 0; kf < 2; kf++) {
            const uint32_t kb2 = kf * 32;   // byte offset of k16 slice
            uint32_t ahi[4][4], alo[4][4];
            uint32_t bhi[4][2], blo[4][2];

            #pragma unroll
            for (int mt = 0; mt < 4; mt++) {
                const uint32_t ro = (wm * 64 + mt * 16) * 80 + a_row_off + kb2;
                ldsm4(ahi[mt], sAhi + ro);
                ldsm4(alo[mt], sAlo + ro);
            }
            #pragma unroll
            for (int pt = 0; pt < 2; pt++) {
                const uint32_t ro = (wn * 32 + pt * 16) * 80 + a_row_off + kb2;
                uint32_t rh[4], rl[4];
                ldsm4(rh, sBhi + ro);
                ldsm4(rl, sBlo + ro);
                bhi[pt * 2][0]     = rh[0]; bhi[pt * 2][1]     = rh[2];
                bhi[pt * 2 + 1][0] = rh[1]; bhi[pt * 2 + 1][1] = rh[3];
                blo[pt * 2][0]     = rl[0]; blo[pt * 2][1]     = rl[2];
                blo[pt * 2 + 1][0] = rl[1]; blo[pt * 2 + 1][1] = rl[3];
            }

            #pragma unroll
            for (int mt = 0; mt < 4; mt++)
                #pragma unroll
                for (int nt = 0; nt < 4; nt++) {
                    mma_bf16(acc[mt][nt], ahi[mt], bhi[nt][0], bhi[nt][1]);  // hi*hi
                    mma_bf16(acc[mt][nt], ahi[mt], blo[nt][0], blo[nt][1]);  // hi*lo
                    mma_bf16(acc[mt][nt], alo[mt], bhi[nt][0], bhi[nt][1]);  // lo*hi
                }
        }
        __syncthreads();
    }

    // ---- epilogue ----
    const int g  = lane >> 2;
    const int tc = (lane & 3) * 2;
    #pragma unroll
    for (int mt = 0; mt < 4; mt++)
        #pragma unroll
        for (int nt = 0; nt < 4; nt++) {
            const int r = m0 + wm * 64 + mt * 16 + g;
            const int c = n0 + wn * 32 + nt * 8 + tc;
            float b0 = 0.f, b1 = 0.f;
            if (bias) { b0 = bias[c]; b1 = bias[c + 1]; }
            float v00 = acc[mt][nt][0] + b0, v01 = acc[mt][nt][1] + b1;
            float v10 = acc[mt][nt][2] + b0, v11 = acc[mt][nt][3] + b1;
            if (Cf) {
                *(float2*)(Cf + (long)r * ldc + c)       = make_float2(v00, v01);
                *(float2*)(Cf + (long)(r + 8) * ldc + c) = make_float2(v10, v11);
            } else {
                __nv_bfloat16 h0, l0, h1, l1;
                split1(v00, h0, l0); split1(v01, h1, l1);
                *(uint32_t*)(Chi + (long)r * ldc + c) = pack2(h0, h1);
                *(uint32_t*)(Clo + (long)r * ldc + c) = pack2(l0, l1);
                split1(v10, h0, l0); split1(v11, h1, l1);
                *(uint32_t*)(Chi + (long)(r + 8) * ldc + c) = pack2(h0, h1);
                *(uint32_t*)(Clo + (long)(r + 8) * ldc + c) = pack2(l0, l1);
            }
        }
}

// ---------------------------------------------------------------------------
// Streaming attention (R4-exact): one CTA per batch element, occ 2.
// ---------------------------------------------------------------------------
__global__ void __launch_bounds__(256, 2) attn_stream(
    const __nv_bfloat16* __restrict__ qthi, const __nv_bfloat16* __restrict__ qtlo,
    const float* __restrict__ k, const float* __restrict__ v,
    __nv_bfloat16* __restrict__ yhi, __nv_bfloat16* __restrict__ ylo)
{
    __shared__ __align__(16) float s_qt[NH * NHID];
    __shared__ __align__(16) float s_p[NH][NM];

    const int b    = blockIdx.x;
    const int tid  = threadIdx.x;
    const int lane = tid & 31;
    const int w    = tid >> 5;

    {
        const __nv_bfloat16* qh = qthi + (long)b * (NH * NHID);
        const __nv_bfloat16* ql = qtlo + (long)b * (NH * NHID);
        #pragma unroll
        for (int i = 0; i < 4; i++) {
            const int idx = tid * 8 + i * 2048;
            uint4 uh = *(const uint4*)(qh + idx);
            uint4 ul = *(const uint4*)(ql + idx);
            const __nv_bfloat16* ph = (const __nv_bfloat16*)&uh;
            const __nv_bfloat16* pl = (const __nv_bfloat16*)&ul;
            float4 f0, f1;
            f0.x = __bfloat162float(ph[0]) + __bfloat162float(pl[0]);
            f0.y = __bfloat162float(ph[1]) + __bfloat162float(pl[1]);
            f0.z = __bfloat162float(ph[2]) + __bfloat162float(pl[2]);
            f0.w = __bfloat162float(ph[3]) + __bfloat162float(pl[3]);
            f1.x = __bfloat162float(ph[4]) + __bfloat162float(pl[4]);
            f1.y = __bfloat162float(ph[5]) + __bfloat162float(pl[5]);
            f1.z = __bfloat162float(ph[6]) + __bfloat162float(pl[6]);
            f1.w = __bfloat162float(ph[7]) + __bfloat162float(pl[7]);
            *(float4*)&s_qt[idx]     = f0;
            *(float4*)&s_qt[idx + 4] = f1;
        }
    }
    __syncthreads();

    {
        const int hg    = (w >> 2) * 4;
        const int mrow0 = (w & 3) * 16;
        const float* kb = k + (long)b * NM * NHID + (long)mrow0 * NHID;
        #pragma unroll 1
        for (int mg = 0; mg < 16; mg += 4) {
            float acc[4][4];
            #pragma unroll
            for (int mi = 0; mi < 4; mi++)
                #pragma unroll
                for (int hh = 0; hh < 4; hh++) acc[mi][hh] = 0.f;

            #pragma unroll 4
            for (int jb = 0; jb < 8; jb++) {
                const int j = jb * 128 + lane * 4;
                float4 kf[4];
                #pragma unroll
                for (int mi = 0; mi < 4; mi++)
                    kf[mi] = *(const float4*)&kb[(long)(mg + mi) * NHID + j];
                float4 qf[4];
                #pragma unroll
                for (int hh = 0; hh < 4; hh++)
                    qf[hh] = *(const float4*)&s_qt[(hg + hh) * NHID + j];
                #pragma unroll
                for (int mi = 0; mi < 4; mi++)
                    #pragma unroll
                    for (int hh = 0; hh < 4; hh++) {
                        acc[mi][hh] += kf[mi].x * qf[hh].x;
                        acc[mi][hh] += kf[mi].y * qf[hh].y;
                        acc[mi][hh] += kf[mi].z * qf[hh].z;
                        acc[mi][hh] += kf[mi].w * qf[hh].w;
                    }
            }
            #pragma unroll
            for (int mi = 0; mi < 4; mi++)
                #pragma unroll
                for (int hh = 0; hh < 4; hh++) {
                    float s = acc[mi][hh];
                    s += __shfl_xor_sync(0xffffffffu, s, 16);
                    s += __shfl_xor_sync(0xffffffffu, s, 8);
                    s += __shfl_xor_sync(0xffffffffu, s, 4);
                    s += __shfl_xor_sync(0xffffffffu, s, 2);
                    s += __shfl_xor_sync(0xffffffffu, s, 1);
                    if (lane == 0) s_p[hg + hh][mrow0 + mg + mi] = s;
                }
        }
    }
    __syncthreads();

    {
        float s0 = s_p[w][lane];
        float s1 = s_p[w][lane + 32];
        float mx = fmaxf(s0, s1);
        #pragma unroll
        for (int o = 16; o > 0; o >>= 1)
            mx = fmaxf(mx, __shfl_xor_sync(0xffffffffu, mx, o));
        float e0 = expf(s0 - mx);
        float e1 = expf(s1 - mx);
        float sum = e0 + e1;
        #pragma unroll
        for (int o = 16; o > 0; o >>= 1)
            sum += __shfl_xor_sync(0xffffffffu, sum, o);
        const float inv = 1.f / sum;
        s_p[w][lane]      = e0 * inv;
        s_p[w][lane + 32] = e1 * inv;
    }
    __syncthreads();

    {
        const int j = w * 128 + lane * 4;
        const float* vb = v + (long)b * NM * NHID;
        float4 acc[NH];
        #pragma unroll
        for (int hh = 0; hh < NH; hh++) acc[hh] = make_float4(0.f, 0.f, 0.f, 0.f);

        #pragma unroll 2
        for (int m = 0; m < NM; m += 4) {
            float4 vf[4];
            #pragma unroll
            for (int mi = 0; mi < 4; mi++)
                vf[mi] = *(const float4*)&vb[(long)(m + mi) * NHID + j];
            #pragma unroll
            for (int hh = 0; hh < NH; hh++) {
                const float4 pa = *(const float4*)&s_p[hh][m];
                acc[hh].x += pa.x * vf[0].x + pa.y * vf[1].x + pa.z * vf[2].x + pa.w * vf[3].x;
                acc[hh].y += pa.x * vf[0].y + pa.y * vf[1].y + pa.z * vf[2].y + pa.w * vf[3].y;
                acc[hh].z += pa.x * vf[0].z + pa.y * vf[1].z + pa.z * vf[2].z + pa.w * vf[3].z;
                acc[hh].w += pa.x * vf[0].w + pa.y * vf[1].w + pa.z * vf[2].w + pa.w * vf[3].w;
            }
        }
        const long yb = (long)b * (NH * NHID);
        #pragma unroll
        for (int hh = 0; hh < NH; hh++) {
            const float4 a = acc[hh];
            __nv_bfloat16 h0, l0, h1, l1, h2, l2, h3, l3;
            split1(a.x, h0, l0); split1(a.y, h1, l1);
            split1(a.z, h2, l2); split1(a.w, h3, l3);
            uint2 uh, ul;
            uh.x = pack2(h0, h1); uh.y = pack2(h2, h3);
            ul.x = pack2(l0, l1); ul.y = pack2(l2, l3);
            *(uint2*)(yhi + yb + hh * NHID + j) = uh;
            *(uint2*)(ylo + yb + hh * NHID + j) = ul;
        }
    }
}

// ---------------------------------------------------------------------------
// Launch (R4-exact order)
// ---------------------------------------------------------------------------
extern "C" void kernel_launch(void* const* d_in, const int* in_sizes, int n_in,
                              void* d_out, int out_size)
{
    const float* q  = (const float*)d_in[0];
    const float* k  = (const float*)d_in[1];
    const float* v  = (const float*)d_in[2];
    const float* Wq = (const float*)d_in[3];
    const float* Wk = (const float*)d_in[4];
    const float* Wv = (const float*)d_in[5];
    const float* Wb = (const float*)d_in[6];
    const float* Wo = (const float*)d_in[7];
    const float* bo = (const float*)d_in[8];
    float* out = (float*)d_out;

    __nv_bfloat16 *qs_hi, *qs_lo, *Wq_hi, *Wq_lo, *Wb_hi, *Wb_lo;
    __nv_bfloat16 *Wkt_hi, *Wkt_lo, *Wv_hi, *Wv_lo, *Wo_hi, *Wo_lo;
    __nv_bfloat16 *qp_hi, *qp_lo, *qb_hi, *qb_lo, *qt_hi, *qt_lo;
    __nv_bfloat16 *y_hi, *y_lo, *x_hi, *x_lo;
    cudaGetSymbolAddress((void**)&qs_hi, g_qs_hi);   cudaGetSymbolAddress((void**)&qs_lo, g_qs_lo);
    cudaGetSymbolAddress((void**)&Wq_hi, g_Wq_hi);   cudaGetSymbolAddress((void**)&Wq_lo, g_Wq_lo);
    cudaGetSymbolAddress((void**)&Wb_hi, g_Wb_hi);   cudaGetSymbolAddress((void**)&Wb_lo, g_Wb_lo);
    cudaGetSymbolAddress((void**)&Wkt_hi, g_Wkt_hi); cudaGetSymbolAddress((void**)&Wkt_lo, g_Wkt_lo);
    cudaGetSymbolAddress((void**)&Wv_hi, g_Wv_hi);   cudaGetSymbolAddress((void**)&Wv_lo, g_Wv_lo);
    cudaGetSymbolAddress((void**)&Wo_hi, g_Wo_hi);   cudaGetSymbolAddress((void**)&Wo_lo, g_Wo_lo);
    cudaGetSymbolAddress((void**)&qp_hi, g_qp_hi);   cudaGetSymbolAddress((void**)&qp_lo, g_qp_lo);
    cudaGetSymbolAddress((void**)&qb_hi, g_qb_hi);   cudaGetSymbolAddress((void**)&qb_lo, g_qb_lo);
    cudaGetSymbolAddress((void**)&qt_hi, g_qt_hi);   cudaGetSymbolAddress((void**)&qt_lo, g_qt_lo);
    cudaGetSymbolAddress((void**)&y_hi,  g_y_hi);    cudaGetSymbolAddress((void**)&y_lo,  g_y_lo);
    cudaGetSymbolAddress((void**)&x_hi,  g_x_hi);    cudaGetSymbolAddress((void**)&x_lo,  g_x_lo);

    cudaFuncSetAttribute(gemm_ldsm, cudaFuncAttributeMaxDynamicSharedMemorySize, GEMM_SMEM);

    dim3 blk(256);

    // conversions (R4-exact)
    split_f32<<<(NB * NHID / 4 + 255) / 256, blk>>>(q, qs_hi, qs_lo, NB * NHID / 4);
    split_f32<<<(NHID * NHID / 4 + 255) / 256, blk>>>(Wq, Wq_hi, Wq_lo, NHID * NHID / 4);
    split_f32<<<(ND * ND / 4 + 255) / 256, blk>>>(Wb, Wb_hi, Wb_lo, ND * ND / 4);
    tsplit_wk<<<dim3(NHID / 32, ND / 32, NH), blk>>>(Wk, Wkt_hi, Wkt_lo);
    split_f32<<<(NHID * NHID / 4 + 255) / 256, blk>>>(Wv, Wv_hi, Wv_lo, NHID * NHID / 4);

    // G1: qp = q @ Wq^T            M=2048 N=1024 K=1024
    gemm_ldsm<<<dim3(16, 8, 1), blk, GEMM_SMEM>>>(
        qs_hi, qs_lo, NHID, 0, Wq_hi, Wq_lo, NHID, 0,
        nullptr, qp_hi, qp_lo, NHID, 0, NHID, nullptr);
    // G2: qb_h = qp_h @ Wb^T       M=2048 N=128 K=128 (per head)
    gemm_ldsm<<<dim3(16, 1, 8), blk, GEMM_SMEM>>>(
        qp_hi, qp_lo, NHID, ND, Wb_hi, Wb_lo, ND, 0,
        nullptr, qb_hi, qb_lo, NHID, ND, ND, nullptr);
    // G3: qt_h = qb_h @ Wkt_h^T    M=2048 N=1024 K=128 (per head)
    gemm_ldsm<<<dim3(16, 8, 8), blk, GEMM_SMEM>>>(
        qb_hi, qb_lo, NHID, ND, Wkt_hi, Wkt_lo, ND, (long)NHID * ND,
        nullptr, qt_hi, qt_lo, NH * NHID, NHID, ND, nullptr);
    // attention
    attn_stream<<<NB, blk>>>(qt_hi, qt_lo, k, v, y_hi, y_lo);
    split_f32<<<(NHID * NHID / 4 + 255) / 256, blk>>>(Wo, Wo_hi, Wo_lo, NHID * NHID / 4);
    // G4: x_h = y_h @ Wv_h^T       M=2048 N=128 K=1024 (per head)
    gemm_ldsm<<<dim3(16, 1, 8), blk, GEMM_SMEM>>>(
        y_hi, y_lo, NH * NHID, NHID, Wv_hi, Wv_lo, NHID, (long)ND * NHID,
        nullptr, x_hi, x_lo, NHID, ND, NHID, nullptr);
    // G5: out = x @ Wo^T + bo      M=2048 N=1024 K=1024
    gemm_ldsm<<<dim3(16, 8, 1), blk, GEMM_SMEM>>>(
        x_hi, x_lo, NHID, 0, Wo_hi, Wo_lo, NHID, 0,
        out, nullptr, nullptr, NHID, 0, NHID, bo);
}